// round 15
// baseline (speedup 1.0000x reference)
#include <cuda_runtime.h>
#include <math.h>

#define BB 2048
#define TT 7
#define NN 90
#define FF 27
#define HH 30
#define NFD 2430
#define NHD 2700

__device__ float g_conf[BB*TT];
__device__ float g_seq[(size_t)TT*BB*NFD];
__device__ float g_final[(size_t)BB*NHD];
__device__ float g_gsum[8*HH];
__device__ float4 g_w4[NN*NN];     // (w0,w1,w2,0) for [in_row i][out_ch o]
__device__ float g_y1[(size_t)BB*1024];
__device__ float g_y2[(size_t)BB*256];
__device__ float g_bn1[2*1024];
__device__ float g_bn2[2*256];

__global__ void k_init(const float* __restrict__ w) {
    int idx = blockIdx.x*blockDim.x + threadIdx.x;
    if (idx < 8*HH) g_gsum[idx] = 0.f;
    if (idx < NN*NN) {
        int i = idx/NN, o = idx%NN;
        const float* p = w + (size_t)(o*NN + i)*3;
        g_w4[idx] = make_float4(p[0], p[1], p[2], 0.f);
    }
}

__global__ void k_conf(const float* __restrict__ fd, const float* __restrict__ unw,
                       const float* __restrict__ unb) {
    int w = (blockIdx.x*blockDim.x + threadIdx.x) >> 5;
    int lane = threadIdx.x & 31;
    if (w >= BB*TT) return;
    int t = w / BB, b = w % BB;
    const float* row = fd + ((size_t)b*TT + t)*NFD;
    float s = 0.f;
    for (int k = lane; k < NFD; k += 32) s += row[k]*unw[k];
    #pragma unroll
    for (int o = 16; o; o >>= 1) s += __shfl_down_sync(0xffffffffu, s, o);
    if (!lane) g_conf[w] = 1.f/(1.f + expf(-(s + unb[0])));
}

__global__ __launch_bounds__(256) void k_att(const float* __restrict__ fd,
        const float* __restrict__ U1, const float* __restrict__ U2,
        const float* __restrict__ U3, const float* __restrict__ be,
        const float* __restrict__ ve) {
    extern __shared__ float sm[];
    float* fs   = sm;
    float* u2s  = fs + 17010;
    float* u1s  = u2s + 2430;
    float* u3s  = u1s + 96;
    float* lhs1 = u3s + 32;
    float* lhs2 = lhs1 + 192;
    float* rhsS = lhs2 + 630;
    float* ps   = rhsS + 630;
    float* sms  = ps + 56;
    float* ta   = sms + 56;

    int b = blockIdx.x, tid = threadIdx.x;
    const float* f0 = fd + (size_t)b*TT*NFD;
    for (int i = tid; i < TT*NFD; i += 256) fs[i] = f0[i];
    for (int i = tid; i < NFD; i += 256) u2s[i] = U2[i];
    if (tid < NN) u1s[tid] = U1[tid];
    if (tid < FF) u3s[tid] = U3[tid];
    __syncthreads();

    for (int i = tid; i < NN*TT; i += 256) {
        int v = i/TT, t = i%TT; float s = 0.f;
        #pragma unroll
        for (int f = 0; f < FF; f++) s += fs[t*NFD + v*FF + f]*u3s[f];
        rhsS[i] = s;
    }
    for (int i = tid; i < TT*FF; i += 256) {
        int t = i/FF, f = i%FF; float s = 0.f;
        for (int v = 0; v < NN; v++) s += fs[t*NFD + v*FF + f]*u1s[v];
        lhs1[i] = s;
    }
    __syncthreads();
    for (int i = tid; i < TT*NN; i += 256) {
        int t = i/NN, n = i%NN; float s = 0.f;
        #pragma unroll
        for (int f = 0; f < FF; f++) s += lhs1[t*FF + f]*u2s[f*NN + n];
        lhs2[i] = s;
    }
    __syncthreads();
    if (tid < 49) {
        int t = tid/TT, s2 = tid%TT; float s = 0.f;
        for (int v = 0; v < NN; v++) s += lhs2[t*NN + v]*rhsS[v*TT + s2];
        ps[tid] = 1.f/(1.f + expf(-(s + be[tid])));
    }
    __syncthreads();
    if (tid < 49) {
        int k = tid/TT, i = tid%TT; float s = 0.f;
        #pragma unroll
        for (int j = 0; j < TT; j++) s += ve[i*TT + j]*ps[k*TT + j];
        sms[k*TT + i] = s;
    }
    __syncthreads();
    if (tid < TT) {
        int i = tid; float mx = -1e30f;
        #pragma unroll
        for (int k = 0; k < TT; k++) mx = fmaxf(mx, sms[k*TT + i]);
        float e[TT]; float den = 0.f;
        #pragma unroll
        for (int k = 0; k < TT; k++) { e[k] = expf(sms[k*TT + i] - mx); den += e[k]; }
        float inv = 1.f/den;
        #pragma unroll
        for (int k = 0; k < TT; k++) ta[k*TT + i] = e[k]*inv;
    }
    __syncthreads();
    for (int j = tid; j < TT*NFD; j += 256) {
        int nf = j/TT, t2 = j%TT;
        float s = 0.f;
        #pragma unroll
        for (int t = 0; t < TT; t++) s += fs[t*NFD + nf]*ta[t*TT + t2];
        int tp = j/NFD, rem = j%NFD;
        g_seq[(size_t)tp*BB*NFD + (size_t)b*NFD + rem] = s;
    }
}

// ---- packed f32x2 helpers (Blackwell FFMA2 via PTX) ----
__device__ __forceinline__ unsigned long long ffma2(unsigned long long a,
        unsigned long long b, unsigned long long c) {
    unsigned long long d;
    asm("fma.rn.f32x2 %0, %1, %2, %3;" : "=l"(d) : "l"(a), "l"(b), "l"(c));
    return d;
}
__device__ __forceinline__ unsigned long long packdup(float x) {
    unsigned long long d; unsigned int u = __float_as_uint(x);
    asm("mov.b64 %0, {%1, %2};" : "=l"(d) : "r"(u), "r"(u));
    return d;
}
__device__ __forceinline__ float2 unpack2(unsigned long long v) {
    unsigned int lo, hi;
    asm("mov.b64 {%0, %1}, %2;" : "=r"(lo), "=r"(hi) : "l"(v));
    return make_float2(__uint_as_float(lo), __uint_as_float(hi));
}

// Packed conv: P output pairs (2P positions), row stride WS floats.
// src points at (padded row base + x0): rv[k] = r[x0-1+k] via the +1 data
// offset. g[q] = LDS.64 of (rv[2q], rv[2q+1]); pair algebra identical for
// both strips -> zero code divergence. Pads are zero -> boundary correct.
template<int P, int WS>
__device__ __forceinline__ void convP(const float* __restrict__ src, int o,
                                      float* __restrict__ out) {
    unsigned long long acc[P];
    #pragma unroll
    for (int p = 0; p < P; p++) acc[p] = 0ull;
    const float4* wp = g_w4 + o;
    #pragma unroll 1
    for (int i = 0; i < NN; i++) {
        float4 w = wp[i*NN];
        unsigned long long w0 = packdup(w.x);
        unsigned long long w1 = packdup(w.y);
        unsigned long long w2 = packdup(w.z);
        const unsigned long long* gp = (const unsigned long long*)(src + i*WS);
        unsigned long long g[P+1];
        #pragma unroll
        for (int q = 0; q <= P; q++) g[q] = gp[q];
        #pragma unroll
        for (int p = 0; p < P; p++) {
            unsigned long long pb = (g[p] >> 32) | (g[p+1] << 32);
            acc[p] = ffma2(w0, g[p],   acc[p]);
            acc[p] = ffma2(w1, pb,     acc[p]);
            acc[p] = ffma2(w2, g[p+1], acc[p]);
        }
    }
    #pragma unroll
    for (int p = 0; p < P; p++) {
        float2 v = unpack2(acc[p]);
        out[2*p] = v.x; out[2*p+1] = v.y;
    }
}

// one block per batch element, called 7x sequentially; 2 CTAs/SM pinned.
// fs: stride 28, data at [row*28+1], pads zero. A2: stride 32, data +1.
__global__ __launch_bounds__(256, 2) void k_st(int t,
        const float* __restrict__ gc1, const float* __restrict__ gc2,
        const float* __restrict__ cb,  const float* __restrict__ lw,
        const float* __restrict__ lbv) {
    extern __shared__ float sm[];
    float* fs    = sm;            // 2528 (90 rows stride 28, +1 offset)
    float* adj   = fs + 2528;     // 8100
    float* L     = adj + 8100;    // 2430
    float* A1    = L + 2430;      // 2700 (stride 30, packed)
    float* A2    = A1 + 2700;     // 2888 (90 rows stride 32, +1 offset)
    float* gc1s  = A2 + 2888;     // 810
    float* gc2s  = gc1s + 810;    // 900
    float* biasS = gc2s + 900;    // 96
    float* gls   = biasS + 96;    // 32
    float* meanS = gls + 32;      // 96
    float* dinvS = meanS + 96;    // 96

    int b = blockIdx.x, tid = threadIdx.x;
    const float* seq = g_seq + (size_t)t*BB*NFD + (size_t)b*NFD;
    const float* gsp = g_gsum + t*HH;

    // single-pass padded fill of fs (no race, no extra barrier)
    for (int i = tid; i < 2528; i += 256) {
        int row = i/28, col = i%28;
        fs[i] = (col >= 1 && row < NN) ? seq[row*FF + col - 1] : 0.f;
    }
    for (int i = tid; i < 2888; i += 256) A2[i] = 0.f;   // pads must be zero
    for (int i = tid; i < FF*HH; i += 256) gc1s[i] = gc1[i];
    for (int i = tid; i < HH*HH; i += 256) gc2s[i] = gc2[i];
    if (tid < NN) biasS[tid] = cb[tid];
    if (tid < FF) {
        const float inv = 1.f/((float)BB*(float)NN);
        float s = lbv[tid];
        #pragma unroll
        for (int h = 0; h < HH; h++) s += lw[tid*HH + h]*gsp[h]*inv;
        gls[tid] = s;
    }
    __syncthreads();

    if (tid < NN) {                                    // row means
        float s = 0.f;
        #pragma unroll
        for (int f = 0; f < FF; f++) s += fs[tid*28 + 1 + f];
        meanS[tid] = s*(1.f/27.f);
    }
    // raw gram into adj: 6x6 register tiles, 225 jobs, single pass
    if (tid < 225) {
        int n0 = (tid/15)*6, m0 = (tid%15)*6;
        float acc[6][6];
        #pragma unroll
        for (int i = 0; i < 6; i++)
            #pragma unroll
            for (int j = 0; j < 6; j++) acc[i][j] = 0.f;
        for (int k = 0; k < FF; k++) {
            float av[6], bv[6];
            #pragma unroll
            for (int j = 0; j < 6; j++) av[j] = fs[(n0+j)*28 + 1 + k];
            #pragma unroll
            for (int j = 0; j < 6; j++) bv[j] = fs[(m0+j)*28 + 1 + k];
            #pragma unroll
            for (int i = 0; i < 6; i++)
                #pragma unroll
                for (int j = 0; j < 6; j++) acc[i][j] += av[i]*bv[j];
        }
        #pragma unroll
        for (int i = 0; i < 6; i++)
            #pragma unroll
            for (int j = 0; j < 6; j++) adj[(n0+i)*NN + m0+j] = acc[i][j];
    }
    __syncthreads();
    if (tid < NN) {
        float mn = meanS[tid];
        dinvS[tid] = rsqrtf(adj[tid*NN + tid] - 27.f*mn*mn);
    }
    __syncthreads();
    for (int i = tid; i < NN*NN; i += 256) {           // normalize -> adj
        int n = i/NN, m = i%NN;
        adj[i] = (adj[i] - 27.f*meanS[n]*meanS[m])*dinvS[n]*dinvS[m];
    }
    // conv1 -> L: packed f32x2, strips x0 in {0,14}, len {14,13}
    if (tid < 180) {
        int o = tid >> 1, half = tid & 1;
        int x0 = half ? 14 : 0, len = half ? 13 : 14;
        float a[14];
        convP<7,28>(fs + x0, o, a);
        float bo = biasS[o];
        #pragma unroll
        for (int j = 0; j < 14; j++)
            if (j < len) L[o*FF + x0 + j] = a[j] + bo + gls[x0 + j];
    }
    __syncthreads();
    // X1 = L @ gc1 -> A1  (180 jobs, 3x5, single pass)
    if (tid < 180) {
        int n0 = (tid/6)*3, h0 = (tid%6)*5;
        float acc0[5] = {0,0,0,0,0}, acc1[5] = {0,0,0,0,0}, acc2[5] = {0,0,0,0,0};
        for (int k = 0; k < FF; k++) {
            float a0 = L[n0*FF + k], a1 = L[(n0+1)*FF + k], a2 = L[(n0+2)*FF + k];
            #pragma unroll
            for (int c = 0; c < 5; c++) {
                float bc = gc1s[k*HH + h0 + c];
                acc0[c] += a0*bc; acc1[c] += a1*bc; acc2[c] += a2*bc;
            }
        }
        #pragma unroll
        for (int c = 0; c < 5; c++) {
            A1[n0*HH + h0 + c] = acc0[c];
            A1[(n0+1)*HH + h0 + c] = acc1[c];
            A1[(n0+2)*HH + h0 + c] = acc2[c];
        }
    }
    __syncthreads();
    // S1 = adj @ X1 -> A2 (stride 32, +1)
    if (tid < 180) {
        int n0 = (tid/6)*3, h0 = (tid%6)*5;
        float acc0[5] = {0,0,0,0,0}, acc1[5] = {0,0,0,0,0}, acc2[5] = {0,0,0,0,0};
        for (int m = 0; m < NN; m++) {
            float a0 = adj[n0*NN + m], a1 = adj[(n0+1)*NN + m], a2 = adj[(n0+2)*NN + m];
            #pragma unroll
            for (int c = 0; c < 5; c++) {
                float bc = A1[m*HH + h0 + c];
                acc0[c] += a0*bc; acc1[c] += a1*bc; acc2[c] += a2*bc;
            }
        }
        #pragma unroll
        for (int c = 0; c < 5; c++) {
            A2[n0*32 + 1 + h0 + c] = acc0[c];
            A2[(n0+1)*32 + 1 + h0 + c] = acc1[c];
            A2[(n0+2)*32 + 1 + h0 + c] = acc2[c];
        }
    }
    __syncthreads();
    // X2 = S1 @ gc2 -> A1
    if (tid < 180) {
        int n0 = (tid/6)*3, h0 = (tid%6)*5;
        float acc0[5] = {0,0,0,0,0}, acc1[5] = {0,0,0,0,0}, acc2[5] = {0,0,0,0,0};
        for (int k = 0; k < HH; k++) {
            float a0 = A2[n0*32 + 1 + k], a1 = A2[(n0+1)*32 + 1 + k], a2 = A2[(n0+2)*32 + 1 + k];
            #pragma unroll
            for (int c = 0; c < 5; c++) {
                float bc = gc2s[k*HH + h0 + c];
                acc0[c] += a0*bc; acc1[c] += a1*bc; acc2[c] += a2*bc;
            }
        }
        #pragma unroll
        for (int c = 0; c < 5; c++) {
            A1[n0*HH + h0 + c] = acc0[c];
            A1[(n0+1)*HH + h0 + c] = acc1[c];
            A1[(n0+2)*HH + h0 + c] = acc2[c];
        }
    }
    __syncthreads();
    // G = adj @ X2 -> A2 (stride 32, +1)
    if (tid < 180) {
        int n0 = (tid/6)*3, h0 = (tid%6)*5;
        float acc0[5] = {0,0,0,0,0}, acc1[5] = {0,0,0,0,0}, acc2[5] = {0,0,0,0,0};
        for (int m = 0; m < NN; m++) {
            float a0 = adj[n0*NN + m], a1 = adj[(n0+1)*NN + m], a2 = adj[(n0+2)*NN + m];
            #pragma unroll
            for (int c = 0; c < 5; c++) {
                float bc = A1[m*HH + h0 + c];
                acc0[c] += a0*bc; acc1[c] += a1*bc; acc2[c] += a2*bc;
            }
        }
        #pragma unroll
        for (int c = 0; c < 5; c++) {
            A2[n0*32 + 1 + h0 + c] = acc0[c];
            A2[(n0+1)*32 + 1 + h0 + c] = acc1[c];
            A2[(n0+2)*32 + 1 + h0 + c] = acc2[c];
        }
    }
    __syncthreads();
    if (tid < HH) {
        float s = 0.f;
        for (int n = 0; n < NN; n++) s += A2[n*32 + 1 + tid];
        atomicAdd(&g_gsum[(t+1)*HH + tid], s);
    }
    // conv2 over G: packed f32x2, strips x0 in {0,16}, len {16,14}
    if (tid < 180) {
        int o = tid >> 1, half = tid & 1;
        int x0 = half ? 16 : 0, len = half ? 14 : 16;
        float a[16];
        convP<8,32>(A2 + x0, o, a);
        float bo = biasS[o];
        float cf = g_conf[b*TT + t];
        float* fo = g_final + (size_t)b*NHD + o*HH;
        if (t == 0) {
            #pragma unroll
            for (int j = 0; j < 16; j++)
                if (j < len) fo[x0 + j] = cf*(a[j] + bo);
        } else {
            #pragma unroll
            for (int j = 0; j < 16; j++)
                if (j < len) fo[x0 + j] += cf*(a[j] + bo);
        }
    }
}

__global__ __launch_bounds__(256) void k_gemm(const float* __restrict__ A,
        const float* __restrict__ W, const float* __restrict__ bias,
        float* __restrict__ C, int M, int N, int K,
        const float* __restrict__ bnp, const float* __restrict__ bg,
        const float* __restrict__ bb) {
    __shared__ float As[16][64];
    __shared__ float Bs[16][64];
    int tid = threadIdx.x;
    int tx = tid & 15, ty = tid >> 4;
    int n0 = blockIdx.x*64, m0 = blockIdx.y*64;
    int lr = tid >> 2, lk = (tid & 3)*4;

    float acc[4][4];
    #pragma unroll
    for (int i = 0; i < 4; i++)
        #pragma unroll
        for (int j = 0; j < 4; j++) acc[i][j] = 0.f;

    for (int k0 = 0; k0 < K; k0 += 16) {
        #pragma unroll
        for (int i = 0; i < 4; i++) {
            int kk = k0 + lk + i;
            float a = 0.f;
            if (kk < K) {
                a = A[(size_t)(m0 + lr)*K + kk];
                if (bnp) a = (a - bnp[kk])*bnp[K + kk]*bg[kk] + bb[kk];
            }
            As[lk + i][lr] = a;
            float w = (kk < K) ? W[(size_t)(n0 + lr)*K + kk] : 0.f;
            Bs[lk + i][lr] = w;
        }
        __syncthreads();
        #pragma unroll
        for (int kk = 0; kk < 16; kk++) {
            float4 a = *(const float4*)&As[kk][ty*4];
            float4 b = *(const float4*)&Bs[kk][tx*4];
            float av[4] = {a.x, a.y, a.z, a.w};
            float bv[4] = {b.x, b.y, b.z, b.w};
            #pragma unroll
            for (int i = 0; i < 4; i++)
                #pragma unroll
                for (int j = 0; j < 4; j++) acc[i][j] += av[i]*bv[j];
        }
        __syncthreads();
    }
    #pragma unroll
    for (int i = 0; i < 4; i++)
        #pragma unroll
        for (int j = 0; j < 4; j++)
            C[(size_t)(m0 + ty*4 + i)*N + n0 + tx*4 + j] = acc[i][j] + bias[n0 + tx*4 + j];
}

__global__ void k_bnstat(const float* __restrict__ Y, int N, float* __restrict__ outp) {
    __shared__ float ss[8][32], qq[8][32];
    int c = threadIdx.x & 31, r0 = threadIdx.x >> 5;
    int col = blockIdx.x*32 + c;
    float s = 0.f, q = 0.f;
    for (int r = r0; r < BB; r += 8) {
        float v = Y[(size_t)r*N + col];
        s += v; q += v*v;
    }
    ss[r0][c] = s; qq[r0][c] = q;
    __syncthreads();
    if (r0 == 0) {
        #pragma unroll
        for (int r = 1; r < 8; r++) { s += ss[r][c]; q += qq[r][c]; }
        float mean = s*(1.f/BB);
        float var = q*(1.f/BB) - mean*mean;
        outp[col] = mean;
        outp[N + col] = rsqrtf(var + 1e-5f);
    }
}

__global__ void k_head(const float* __restrict__ l3w, const float* __restrict__ l3b,
                       const float* __restrict__ bg, const float* __restrict__ bb,
                       float* __restrict__ out) {
    int b = blockIdx.x*8 + (threadIdx.x >> 5);
    int lane = threadIdx.x & 31;
    float a0 = 0.f, a1 = 0.f;
    for (int c = lane; c < 256; c += 32) {
        float v = (g_y2[(size_t)b*256 + c] - g_bn2[c])*g_bn2[256 + c]*bg[c] + bb[c];
        a0 += v*l3w[c];
        a1 += v*l3w[256 + c];
    }
    #pragma unroll
    for (int o = 16; o; o >>= 1) {
        a0 += __shfl_down_sync(0xffffffffu, a0, o);
        a1 += __shfl_down_sync(0xffffffffu, a1, o);
    }
    if (!lane) {
        float z0 = a0 + l3b[0], z1 = a1 + l3b[1];
        float mx = fmaxf(z0, z1);
        float e0 = expf(z0 - mx), e1 = expf(z1 - mx);
        float inv = 1.f/(e0 + e1);
        out[b*2 + 0] = e0*inv;
        out[b*2 + 1] = e1*inv;
    }
}

extern "C" void kernel_launch(void* const* d_in, const int* in_sizes, int n_in,
                              void* d_out, int out_size) {
    const float* fdata = (const float*)d_in[0];
    const float* un_w  = (const float*)d_in[1];
    const float* un_b  = (const float*)d_in[2];
    const float* U1    = (const float*)d_in[3];
    const float* U2    = (const float*)d_in[4];
    const float* U3    = (const float*)d_in[5];
    const float* b_e   = (const float*)d_in[6];
    const float* v_e   = (const float*)d_in[7];
    const float* gc1   = (const float*)d_in[8];
    const float* gc2   = (const float*)d_in[9];
    const float* cnn1w = (const float*)d_in[10];
    const float* cnn1b = (const float*)d_in[11];
    const float* lin_w = (const float*)d_in[12];
    const float* lin_b = (const float*)d_in[13];
    const float* l1_w  = (const float*)d_in[14];
    const float* l1_b  = (const float*)d_in[15];
    const float* bn1g  = (const float*)d_in[16];
    const float* bn1b  = (const float*)d_in[17];
    const float* l2_w  = (const float*)d_in[18];
    const float* l2_b  = (const float*)d_in[19];
    const float* bn2g  = (const float*)d_in[20];
    const float* bn2b  = (const float*)d_in[21];
    const float* l3_w  = (const float*)d_in[22];
    const float* l3_b  = (const float*)d_in[23];
    float* out = (float*)d_out;

    static float* d_bn1p = nullptr;
    static float* d_bn2p = nullptr;
    static float* d_y1p = nullptr;
    static float* d_y2p = nullptr;
    if (!d_bn1p) {
        cudaGetSymbolAddress((void**)&d_bn1p, g_bn1);
        cudaGetSymbolAddress((void**)&d_bn2p, g_bn2);
        cudaGetSymbolAddress((void**)&d_y1p, g_y1);
        cudaGetSymbolAddress((void**)&d_y2p, g_y2);
        cudaFuncSetAttribute(k_att, cudaFuncAttributeMaxDynamicSharedMemorySize, 85000);
        cudaFuncSetAttribute(k_st,  cudaFuncAttributeMaxDynamicSharedMemorySize, 83000);
    }
    float* d_finalp; cudaGetSymbolAddress((void**)&d_finalp, g_final);

    k_init<<<(NN*NN + 255)/256, 256>>>(cnn1w);
    k_conf<<<(BB*TT*32 + 255)/256, 256>>>(fdata, un_w, un_b);
    k_att<<<BB, 256, 21188*4>>>(fdata, U1, U2, U3, b_e, v_e);
    for (int t = 0; t < TT; t++)
        k_st<<<BB, 256, 20676*4>>>(t, gc1, gc2, cnn1b, lin_w, lin_b);
    dim3 g1(1024/64, BB/64);
    k_gemm<<<g1, 256>>>(d_finalp, l1_w, l1_b, d_y1p, BB, 1024, NHD,
                        nullptr, nullptr, nullptr);
    k_bnstat<<<1024/32, 256>>>(d_y1p, 1024, d_bn1p);
    dim3 g2(256/64, BB/64);
    k_gemm<<<g2, 256>>>(d_y1p, l2_w, l2_b, d_y2p, BB, 256, 1024,
                        d_bn1p, bn1g, bn1b);
    k_bnstat<<<256/32, 256>>>(d_y2p, 256, d_bn2p);
    k_head<<<BB/8, 256>>>(l3_w, l3_b, bn2g, bn2b, out);
}

// round 16
// speedup vs baseline: 1.0898x; 1.0898x over previous
#include <cuda_runtime.h>
#include <math.h>

#define BB 2048
#define TT 7
#define NN 90
#define FF 27
#define HH 30
#define NFD 2430
#define NHD 2700

__device__ float g_conf[BB*TT];
__device__ float g_seq[(size_t)TT*BB*NFD];
__device__ float g_final[(size_t)BB*NHD];
__device__ float g_gsum[8*HH];
__device__ float4 g_w4[NN*NN];     // (w0,w1,w2,0) for [in_row i][out_ch o]
__device__ float g_y1[(size_t)BB*1024];
__device__ float g_y2[(size_t)BB*256];
__device__ float g_bn1[2*1024];
__device__ float g_bn2[2*256];

__global__ void k_init(const float* __restrict__ w) {
    int idx = blockIdx.x*blockDim.x + threadIdx.x;
    if (idx < 8*HH) g_gsum[idx] = 0.f;
    if (idx < NN*NN) {
        int i = idx/NN, o = idx%NN;
        const float* p = w + (size_t)(o*NN + i)*3;
        g_w4[idx] = make_float4(p[0], p[1], p[2], 0.f);
    }
}

// k_att with fused conf (warps 0-6 compute the uncertainty dots from smem)
__global__ __launch_bounds__(256) void k_att(const float* __restrict__ fd,
        const float* __restrict__ U1, const float* __restrict__ U2,
        const float* __restrict__ U3, const float* __restrict__ be,
        const float* __restrict__ ve, const float* __restrict__ unw,
        const float* __restrict__ unb) {
    extern __shared__ float sm[];
    float* fs   = sm;
    float* u2s  = fs + 17010;
    float* u1s  = u2s + 2430;
    float* u3s  = u1s + 96;
    float* lhs1 = u3s + 32;
    float* lhs2 = lhs1 + 192;
    float* rhsS = lhs2 + 630;
    float* ps   = rhsS + 630;
    float* sms  = ps + 56;
    float* ta   = sms + 56;

    int b = blockIdx.x, tid = threadIdx.x;
    const float* f0 = fd + (size_t)b*TT*NFD;
    for (int i = tid; i < TT*NFD; i += 256) fs[i] = f0[i];
    for (int i = tid; i < NFD; i += 256) u2s[i] = U2[i];
    if (tid < NN) u1s[tid] = U1[tid];
    if (tid < FF) u3s[tid] = U3[tid];
    __syncthreads();

    // fused conf: warp t computes dot(fdata[b][t], unw); store matches the
    // reference's raw (T*B) reshape: g_conf[t*BB + b]
    if (tid < 224) {
        int t = tid >> 5, lane = tid & 31;
        float s = 0.f;
        for (int k = lane; k < NFD; k += 32) s += fs[t*NFD + k]*unw[k];
        #pragma unroll
        for (int o = 16; o; o >>= 1) s += __shfl_down_sync(0xffffffffu, s, o);
        if (!lane) g_conf[t*BB + b] = 1.f/(1.f + expf(-(s + unb[0])));
    }

    for (int i = tid; i < NN*TT; i += 256) {
        int v = i/TT, t = i%TT; float s = 0.f;
        #pragma unroll
        for (int f = 0; f < FF; f++) s += fs[t*NFD + v*FF + f]*u3s[f];
        rhsS[i] = s;
    }
    for (int i = tid; i < TT*FF; i += 256) {
        int t = i/FF, f = i%FF; float s = 0.f;
        for (int v = 0; v < NN; v++) s += fs[t*NFD + v*FF + f]*u1s[v];
        lhs1[i] = s;
    }
    __syncthreads();
    for (int i = tid; i < TT*NN; i += 256) {
        int t = i/NN, n = i%NN; float s = 0.f;
        #pragma unroll
        for (int f = 0; f < FF; f++) s += lhs1[t*FF + f]*u2s[f*NN + n];
        lhs2[i] = s;
    }
    __syncthreads();
    if (tid < 49) {
        int t = tid/TT, s2 = tid%TT; float s = 0.f;
        for (int v = 0; v < NN; v++) s += lhs2[t*NN + v]*rhsS[v*TT + s2];
        ps[tid] = 1.f/(1.f + expf(-(s + be[tid])));
    }
    __syncthreads();
    if (tid < 49) {
        int k = tid/TT, i = tid%TT; float s = 0.f;
        #pragma unroll
        for (int j = 0; j < TT; j++) s += ve[i*TT + j]*ps[k*TT + j];
        sms[k*TT + i] = s;
    }
    __syncthreads();
    if (tid < TT) {
        int i = tid; float mx = -1e30f;
        #pragma unroll
        for (int k = 0; k < TT; k++) mx = fmaxf(mx, sms[k*TT + i]);
        float e[TT]; float den = 0.f;
        #pragma unroll
        for (int k = 0; k < TT; k++) { e[k] = expf(sms[k*TT + i] - mx); den += e[k]; }
        float inv = 1.f/den;
        #pragma unroll
        for (int k = 0; k < TT; k++) ta[k*TT + i] = e[k]*inv;
    }
    __syncthreads();
    for (int j = tid; j < TT*NFD; j += 256) {
        int nf = j/TT, t2 = j%TT;
        float s = 0.f;
        #pragma unroll
        for (int t = 0; t < TT; t++) s += fs[t*NFD + nf]*ta[t*TT + t2];
        int tp = j/NFD, rem = j%NFD;
        g_seq[(size_t)tp*BB*NFD + (size_t)b*NFD + rem] = s;
    }
}

// conv strip: single code path (runtime x0), compile-time LEN/W (register accs).
// Weights: ONE LDG.128 per input row; i-loop unrolled 2 for MLP. (R14 version)
template<int LEN, int W>
__device__ __forceinline__ void convAccR(const float* __restrict__ src,
                                         float* __restrict__ acc, int o, int x0) {
    #pragma unroll
    for (int j = 0; j < LEN; j++) acc[j] = 0.f;
    const float4* wp = g_w4 + o;
    #pragma unroll 2
    for (int i = 0; i < NN; i++) {
        float4 w = wp[i*NN];
        const float* r = src + i*W;
        float prev = (x0 > 0) ? r[x0-1] : 0.f;
        float cur  = r[x0];
        #pragma unroll
        for (int j = 0; j < LEN; j++) {
            float nxt = (x0 + j + 1 < W) ? r[x0 + j + 1] : 0.f;
            acc[j] += w.x*prev + w.y*cur + w.z*nxt;
            prev = cur; cur = nxt;
        }
    }
}

// one block per batch element, called 7x sequentially; 2 CTAs/SM pinned. (R14)
__global__ __launch_bounds__(256, 2) void k_st(int t,
        const float* __restrict__ gc1, const float* __restrict__ gc2,
        const float* __restrict__ cb,  const float* __restrict__ lw,
        const float* __restrict__ lbv) {
    extern __shared__ float sm[];
    float* fs    = sm;            // 2484 (only 2430 used)
    float* adj   = fs + 2484;     // 8100
    float* L     = adj + 8100;    // 2430
    float* A1    = L + 2430;      // 2700
    float* A2    = A1 + 2700;     // 2700
    float* gc1s  = A2 + 2700;     // 810
    float* gc2s  = gc1s + 810;    // 900
    float* biasS = gc2s + 900;    // 96
    float* gls   = biasS + 96;    // 32
    float* meanS = gls + 32;      // 96
    float* dinvS = meanS + 96;    // 96

    int b = blockIdx.x, tid = threadIdx.x;
    const float* seq = g_seq + (size_t)t*BB*NFD + (size_t)b*NFD;
    const float* gsp = g_gsum + t*HH;

    for (int i = tid; i < NFD/2; i += 256)
        ((float2*)fs)[i] = ((const float2*)seq)[i];
    for (int i = tid; i < FF*HH; i += 256) gc1s[i] = gc1[i];
    for (int i = tid; i < HH*HH; i += 256) gc2s[i] = gc2[i];
    if (tid < NN) biasS[tid] = cb[tid];
    if (tid < FF) {
        const float inv = 1.f/((float)BB*(float)NN);
        float s = lbv[tid];
        #pragma unroll
        for (int h = 0; h < HH; h++) s += lw[tid*HH + h]*gsp[h]*inv;
        gls[tid] = s;
    }
    __syncthreads();

    if (tid < NN) {
        float s = 0.f;
        #pragma unroll
        for (int f = 0; f < FF; f++) s += fs[tid*FF + f];
        meanS[tid] = s*(1.f/27.f);
    }
    if (tid < 225) {                 // gram 6x6 tiles, single pass
        int n0 = (tid/15)*6, m0 = (tid%15)*6;
        float acc[6][6];
        #pragma unroll
        for (int i = 0; i < 6; i++)
            #pragma unroll
            for (int j = 0; j < 6; j++) acc[i][j] = 0.f;
        for (int k = 0; k < FF; k++) {
            float av[6], bv[6];
            #pragma unroll
            for (int j = 0; j < 6; j++) av[j] = fs[(n0+j)*FF + k];
            #pragma unroll
            for (int j = 0; j < 6; j++) bv[j] = fs[(m0+j)*FF + k];
            #pragma unroll
            for (int i = 0; i < 6; i++)
                #pragma unroll
                for (int j = 0; j < 6; j++) acc[i][j] += av[i]*bv[j];
        }
        #pragma unroll
        for (int i = 0; i < 6; i++)
            #pragma unroll
            for (int j = 0; j < 6; j++) adj[(n0+i)*NN + m0+j] = acc[i][j];
    }
    __syncthreads();
    if (tid < NN) {
        float mn = meanS[tid];
        dinvS[tid] = rsqrtf(adj[tid*NN + tid] - 27.f*mn*mn);
    }
    __syncthreads();
    for (int i = tid; i < NN*NN; i += 256) {
        int n = i/NN, m = i%NN;
        adj[i] = (adj[i] - 27.f*meanS[n]*meanS[m])*dinvS[n]*dinvS[m];
    }
    if (tid < 180) {                 // conv1 -> L
        int o = tid >> 1, half = tid & 1;
        int x0 = half ? 13 : 0, len = half ? 14 : 13;
        float a[14];
        convAccR<14,FF>(fs, a, o, x0);
        float bo = biasS[o];
        #pragma unroll
        for (int j = 0; j < 14; j++)
            if (j < len) L[o*FF + x0 + j] = a[j] + bo + gls[x0 + j];
    }
    __syncthreads();
    if (tid < 180) {                 // X1 = L @ gc1 -> A1
        int n0 = (tid/6)*3, h0 = (tid%6)*5;
        float acc0[5] = {0,0,0,0,0}, acc1[5] = {0,0,0,0,0}, acc2[5] = {0,0,0,0,0};
        for (int k = 0; k < FF; k++) {
            float a0 = L[n0*FF + k], a1 = L[(n0+1)*FF + k], a2 = L[(n0+2)*FF + k];
            #pragma unroll
            for (int c = 0; c < 5; c++) {
                float bc = gc1s[k*HH + h0 + c];
                acc0[c] += a0*bc; acc1[c] += a1*bc; acc2[c] += a2*bc;
            }
        }
        #pragma unroll
        for (int c = 0; c < 5; c++) {
            A1[n0*HH + h0 + c] = acc0[c];
            A1[(n0+1)*HH + h0 + c] = acc1[c];
            A1[(n0+2)*HH + h0 + c] = acc2[c];
        }
    }
    __syncthreads();
    if (tid < 180) {                 // S1 = adj @ X1 -> A2
        int n0 = (tid/6)*3, h0 = (tid%6)*5;
        float acc0[5] = {0,0,0,0,0}, acc1[5] = {0,0,0,0,0}, acc2[5] = {0,0,0,0,0};
        for (int m = 0; m < NN; m++) {
            float a0 = adj[n0*NN + m], a1 = adj[(n0+1)*NN + m], a2 = adj[(n0+2)*NN + m];
            #pragma unroll
            for (int c = 0; c < 5; c++) {
                float bc = A1[m*HH + h0 + c];
                acc0[c] += a0*bc; acc1[c] += a1*bc; acc2[c] += a2*bc;
            }
        }
        #pragma unroll
        for (int c = 0; c < 5; c++) {
            A2[n0*HH + h0 + c] = acc0[c];
            A2[(n0+1)*HH + h0 + c] = acc1[c];
            A2[(n0+2)*HH + h0 + c] = acc2[c];
        }
    }
    __syncthreads();
    if (tid < 180) {                 // X2 = S1 @ gc2 -> A1
        int n0 = (tid/6)*3, h0 = (tid%6)*5;
        float acc0[5] = {0,0,0,0,0}, acc1[5] = {0,0,0,0,0}, acc2[5] = {0,0,0,0,0};
        for (int k = 0; k < HH; k++) {
            float a0 = A2[n0*HH + k], a1 = A2[(n0+1)*HH + k], a2 = A2[(n0+2)*HH + k];
            #pragma unroll
            for (int c = 0; c < 5; c++) {
                float bc = gc2s[k*HH + h0 + c];
                acc0[c] += a0*bc; acc1[c] += a1*bc; acc2[c] += a2*bc;
            }
        }
        #pragma unroll
        for (int c = 0; c < 5; c++) {
            A1[n0*HH + h0 + c] = acc0[c];
            A1[(n0+1)*HH + h0 + c] = acc1[c];
            A1[(n0+2)*HH + h0 + c] = acc2[c];
        }
    }
    __syncthreads();
    if (tid < 180) {                 // G = adj @ X2 -> A2
        int n0 = (tid/6)*3, h0 = (tid%6)*5;
        float acc0[5] = {0,0,0,0,0}, acc1[5] = {0,0,0,0,0}, acc2[5] = {0,0,0,0,0};
        for (int m = 0; m < NN; m++) {
            float a0 = adj[n0*NN + m], a1 = adj[(n0+1)*NN + m], a2 = adj[(n0+2)*NN + m];
            #pragma unroll
            for (int c = 0; c < 5; c++) {
                float bc = A1[m*HH + h0 + c];
                acc0[c] += a0*bc; acc1[c] += a1*bc; acc2[c] += a2*bc;
            }
        }
        #pragma unroll
        for (int c = 0; c < 5; c++) {
            A2[n0*HH + h0 + c] = acc0[c];
            A2[(n0+1)*HH + h0 + c] = acc1[c];
            A2[(n0+2)*HH + h0 + c] = acc2[c];
        }
    }
    __syncthreads();
    if (tid < HH) {
        float s = 0.f;
        for (int n = 0; n < NN; n++) s += A2[n*HH + tid];
        atomicAdd(&g_gsum[(t+1)*HH + tid], s);
    }
    if (tid < 180) {                 // conv2 + conf-weighted accumulate
        int o = tid >> 1, half = tid & 1;
        int x0 = half*15;
        float a[15];
        convAccR<15,HH>(A2, a, o, x0);
        float bo = biasS[o];
        float cf = g_conf[b*TT + t];
        float* fo = g_final + (size_t)b*NHD + o*HH + x0;
        if (t == 0) {
            #pragma unroll
            for (int j = 0; j < 15; j++) fo[j] = cf*(a[j] + bo);
        } else {
            #pragma unroll
            for (int j = 0; j < 15; j++) fo[j] += cf*(a[j] + bo);
        }
    }
}

// C[M,N] = A(BN-opt)[M,K] @ W[N,K]^T + bias. 128x64 tile, 8x4 micro-tile.
__global__ __launch_bounds__(256) void k_gemm(const float* __restrict__ A,
        const float* __restrict__ W, const float* __restrict__ bias,
        float* __restrict__ C, int M, int N, int K,
        const float* __restrict__ bnp, const float* __restrict__ bg,
        const float* __restrict__ bb) {
    __shared__ float As[16][128];
    __shared__ float Bs[16][64];
    int tid = threadIdx.x;
    int tx = tid & 15, ty = tid >> 4;          // 16x16 -> 4-col x 8-row tiles
    int n0 = blockIdx.x*64, m0 = blockIdx.y*128;
    int lrA = tid >> 1, lkA = (tid & 1)*8;     // A: 128 rows, 8 k each
    int lrB = tid >> 2, lkB = (tid & 3)*4;     // B: 64 rows, 4 k each

    float acc[8][4];
    #pragma unroll
    for (int i = 0; i < 8; i++)
        #pragma unroll
        for (int j = 0; j < 4; j++) acc[i][j] = 0.f;

    for (int k0 = 0; k0 < K; k0 += 16) {
        #pragma unroll
        for (int i = 0; i < 8; i++) {
            int kk = k0 + lkA + i;
            float a = 0.f;
            if (kk < K) {
                a = A[(size_t)(m0 + lrA)*K + kk];
                if (bnp) a = (a - bnp[kk])*bnp[K + kk]*bg[kk] + bb[kk];
            }
            As[lkA + i][lrA] = a;
        }
        #pragma unroll
        for (int i = 0; i < 4; i++) {
            int kk = k0 + lkB + i;
            Bs[lkB + i][lrB] = (kk < K) ? W[(size_t)(n0 + lrB)*K + kk] : 0.f;
        }
        __syncthreads();
        #pragma unroll
        for (int kk = 0; kk < 16; kk++) {
            float4 a0 = *(const float4*)&As[kk][ty*8];
            float4 a1 = *(const float4*)&As[kk][ty*8 + 4];
            float4 bv = *(const float4*)&Bs[kk][tx*4];
            float av[8] = {a0.x, a0.y, a0.z, a0.w, a1.x, a1.y, a1.z, a1.w};
            float bw[4] = {bv.x, bv.y, bv.z, bv.w};
            #pragma unroll
            for (int i = 0; i < 8; i++)
                #pragma unroll
                for (int j = 0; j < 4; j++) acc[i][j] += av[i]*bw[j];
        }
        __syncthreads();
    }
    float4 bia = *(const float4*)&bias[n0 + tx*4];
    #pragma unroll
    for (int i = 0; i < 8; i++) {
        float4 v = make_float4(acc[i][0] + bia.x, acc[i][1] + bia.y,
                               acc[i][2] + bia.z, acc[i][3] + bia.w);
        *(float4*)&C[(size_t)(m0 + ty*8 + i)*N + n0 + tx*4] = v;
    }
}

__global__ void k_bnstat(const float* __restrict__ Y, int N, float* __restrict__ outp) {
    __shared__ float ss[8][32], qq[8][32];
    int c = threadIdx.x & 31, r0 = threadIdx.x >> 5;
    int col = blockIdx.x*32 + c;
    float s = 0.f, q = 0.f;
    for (int r = r0; r < BB; r += 8) {
        float v = Y[(size_t)r*N + col];
        s += v; q += v*v;
    }
    ss[r0][c] = s; qq[r0][c] = q;
    __syncthreads();
    if (r0 == 0) {
        #pragma unroll
        for (int r = 1; r < 8; r++) { s += ss[r][c]; q += qq[r][c]; }
        float mean = s*(1.f/BB);
        float var = q*(1.f/BB) - mean*mean;
        outp[col] = mean;
        outp[N + col] = rsqrtf(var + 1e-5f);
    }
}

__global__ void k_head(const float* __restrict__ l3w, const float* __restrict__ l3b,
                       const float* __restrict__ bg, const float* __restrict__ bb,
                       float* __restrict__ out) {
    int b = blockIdx.x*8 + (threadIdx.x >> 5);
    int lane = threadIdx.x & 31;
    float a0 = 0.f, a1 = 0.f;
    for (int c = lane; c < 256; c += 32) {
        float v = (g_y2[(size_t)b*256 + c] - g_bn2[c])*g_bn2[256 + c]*bg[c] + bb[c];
        a0 += v*l3w[c];
        a1 += v*l3w[256 + c];
    }
    #pragma unroll
    for (int o = 16; o; o >>= 1) {
        a0 += __shfl_down_sync(0xffffffffu, a0, o);
        a1 += __shfl_down_sync(0xffffffffu, a1, o);
    }
    if (!lane) {
        float z0 = a0 + l3b[0], z1 = a1 + l3b[1];
        float mx = fmaxf(z0, z1);
        float e0 = expf(z0 - mx), e1 = expf(z1 - mx);
        float inv = 1.f/(e0 + e1);
        out[b*2 + 0] = e0*inv;
        out[b*2 + 1] = e1*inv;
    }
}

extern "C" void kernel_launch(void* const* d_in, const int* in_sizes, int n_in,
                              void* d_out, int out_size) {
    const float* fdata = (const float*)d_in[0];
    const float* un_w  = (const float*)d_in[1];
    const float* un_b  = (const float*)d_in[2];
    const float* U1    = (const float*)d_in[3];
    const float* U2    = (const float*)d_in[4];
    const float* U3    = (const float*)d_in[5];
    const float* b_e   = (const float*)d_in[6];
    const float* v_e   = (const float*)d_in[7];
    const float* gc1   = (const float*)d_in[8];
    const float* gc2   = (const float*)d_in[9];
    const float* cnn1w = (const float*)d_in[10];
    const float* cnn1b = (const float*)d_in[11];
    const float* lin_w = (const float*)d_in[12];
    const float* lin_b = (const float*)d_in[13];
    const float* l1_w  = (const float*)d_in[14];
    const float* l1_b  = (const float*)d_in[15];
    const float* bn1g  = (const float*)d_in[16];
    const float* bn1b  = (const float*)d_in[17];
    const float* l2_w  = (const float*)d_in[18];
    const float* l2_b  = (const float*)d_in[19];
    const float* bn2g  = (const float*)d_in[20];
    const float* bn2b  = (const float*)d_in[21];
    const float* l3_w  = (const float*)d_in[22];
    const float* l3_b  = (const float*)d_in[23];
    float* out = (float*)d_out;

    static float* d_bn1p = nullptr;
    static float* d_bn2p = nullptr;
    static float* d_y1p = nullptr;
    static float* d_y2p = nullptr;
    if (!d_bn1p) {
        cudaGetSymbolAddress((void**)&d_bn1p, g_bn1);
        cudaGetSymbolAddress((void**)&d_bn2p, g_bn2);
        cudaGetSymbolAddress((void**)&d_y1p, g_y1);
        cudaGetSymbolAddress((void**)&d_y2p, g_y2);
        cudaFuncSetAttribute(k_att, cudaFuncAttributeMaxDynamicSharedMemorySize, 85000);
        cudaFuncSetAttribute(k_st,  cudaFuncAttributeMaxDynamicSharedMemorySize, 82000);
    }
    float* d_finalp; cudaGetSymbolAddress((void**)&d_finalp, g_final);

    k_init<<<(NN*NN + 255)/256, 256>>>(cnn1w);
    k_att<<<BB, 256, 21188*4>>>(fdata, U1, U2, U3, b_e, v_e, un_w, un_b);
    for (int t = 0; t < TT; t++)
        k_st<<<BB, 256, 20444*4>>>(t, gc1, gc2, cnn1b, lin_w, lin_b);
    dim3 g1(1024/64, BB/128);
    k_gemm<<<g1, 256>>>(d_finalp, l1_w, l1_b, d_y1p, BB, 1024, NHD,
                        nullptr, nullptr, nullptr);
    k_bnstat<<<1024/32, 256>>>(d_y1p, 1024, d_bn1p);
    dim3 g2(256/64, BB/128);
    k_gemm<<<g2, 256>>>(d_y1p, l2_w, l2_b, d_y2p, BB, 256, 1024,
                        d_bn1p, bn1g, bn1b);
    k_bnstat<<<256/32, 256>>>(d_y2p, 256, d_bn2p);
    k_head<<<BB/8, 256>>>(l3_w, l3_b, bn2g, bn2b, out);
}

// round 17
// speedup vs baseline: 1.1696x; 1.0732x over previous
#include <cuda_runtime.h>
#include <math.h>

#define BB 2048
#define TT 7
#define NN 90
#define FF 27
#define HH 30
#define NFD 2430
#define NHD 2700

__device__ float g_conf[BB*TT];
__device__ float g_seq[(size_t)TT*BB*NFD];
__device__ float g_final[(size_t)BB*NHD];
__device__ float g_gsum[8*HH];
__device__ float4 g_w4[NN*NN];     // (w0,w1,w2,0) for [in_row i][out_ch o]
__device__ float g_y1[(size_t)BB*1024];
__device__ float g_y2[(size_t)BB*256];
__device__ float g_bn1[2*1024];
__device__ float g_bn2[2*256];

__global__ void k_init(const float* __restrict__ w) {
    int idx = blockIdx.x*blockDim.x + threadIdx.x;
    if (idx < 8*HH) g_gsum[idx] = 0.f;
    if (idx < NN*NN) {
        int i = idx/NN, o = idx%NN;
        const float* p = w + (size_t)(o*NN + i)*3;
        g_w4[idx] = make_float4(p[0], p[1], p[2], 0.f);
    }
}

// k_att with fused conf (warps 0-6 compute the uncertainty dots from smem)
__global__ __launch_bounds__(256) void k_att(const float* __restrict__ fd,
        const float* __restrict__ U1, const float* __restrict__ U2,
        const float* __restrict__ U3, const float* __restrict__ be,
        const float* __restrict__ ve, const float* __restrict__ unw,
        const float* __restrict__ unb) {
    extern __shared__ float sm[];
    float* fs   = sm;
    float* u2s  = fs + 17010;
    float* u1s  = u2s + 2430;
    float* u3s  = u1s + 96;
    float* lhs1 = u3s + 32;
    float* lhs2 = lhs1 + 192;
    float* rhsS = lhs2 + 630;
    float* ps   = rhsS + 630;
    float* sms  = ps + 56;
    float* ta   = sms + 56;

    int b = blockIdx.x, tid = threadIdx.x;
    const float* f0 = fd + (size_t)b*TT*NFD;
    for (int i = tid; i < TT*NFD; i += 256) fs[i] = f0[i];
    for (int i = tid; i < NFD; i += 256) u2s[i] = U2[i];
    if (tid < NN) u1s[tid] = U1[tid];
    if (tid < FF) u3s[tid] = U3[tid];
    __syncthreads();

    if (tid < 224) {
        int t = tid >> 5, lane = tid & 31;
        float s = 0.f;
        for (int k = lane; k < NFD; k += 32) s += fs[t*NFD + k]*unw[k];
        #pragma unroll
        for (int o = 16; o; o >>= 1) s += __shfl_down_sync(0xffffffffu, s, o);
        if (!lane) g_conf[t*BB + b] = 1.f/(1.f + expf(-(s + unb[0])));
    }

    for (int i = tid; i < NN*TT; i += 256) {
        int v = i/TT, t = i%TT; float s = 0.f;
        #pragma unroll
        for (int f = 0; f < FF; f++) s += fs[t*NFD + v*FF + f]*u3s[f];
        rhsS[i] = s;
    }
    for (int i = tid; i < TT*FF; i += 256) {
        int t = i/FF, f = i%FF; float s = 0.f;
        for (int v = 0; v < NN; v++) s += fs[t*NFD + v*FF + f]*u1s[v];
        lhs1[i] = s;
    }
    __syncthreads();
    for (int i = tid; i < TT*NN; i += 256) {
        int t = i/NN, n = i%NN; float s = 0.f;
        #pragma unroll
        for (int f = 0; f < FF; f++) s += lhs1[t*FF + f]*u2s[f*NN + n];
        lhs2[i] = s;
    }
    __syncthreads();
    if (tid < 49) {
        int t = tid/TT, s2 = tid%TT; float s = 0.f;
        for (int v = 0; v < NN; v++) s += lhs2[t*NN + v]*rhsS[v*TT + s2];
        ps[tid] = 1.f/(1.f + expf(-(s + be[tid])));
    }
    __syncthreads();
    if (tid < 49) {
        int k = tid/TT, i = tid%TT; float s = 0.f;
        #pragma unroll
        for (int j = 0; j < TT; j++) s += ve[i*TT + j]*ps[k*TT + j];
        sms[k*TT + i] = s;
    }
    __syncthreads();
    if (tid < TT) {
        int i = tid; float mx = -1e30f;
        #pragma unroll
        for (int k = 0; k < TT; k++) mx = fmaxf(mx, sms[k*TT + i]);
        float e[TT]; float den = 0.f;
        #pragma unroll
        for (int k = 0; k < TT; k++) { e[k] = expf(sms[k*TT + i] - mx); den += e[k]; }
        float inv = 1.f/den;
        #pragma unroll
        for (int k = 0; k < TT; k++) ta[k*TT + i] = e[k]*inv;
    }
    __syncthreads();
    for (int j = tid; j < TT*NFD; j += 256) {
        int nf = j/TT, t2 = j%TT;
        float s = 0.f;
        #pragma unroll
        for (int t = 0; t < TT; t++) s += fs[t*NFD + nf]*ta[t*TT + t2];
        int tp = j/NFD, rem = j%NFD;
        g_seq[(size_t)tp*BB*NFD + (size_t)b*NFD + rem] = s;
    }
}

// conv strip: single code path (runtime x0), compile-time LEN/W (register accs).
template<int LEN, int W>
__device__ __forceinline__ void convAccR(const float* __restrict__ src,
                                         float* __restrict__ acc, int o, int x0) {
    #pragma unroll
    for (int j = 0; j < LEN; j++) acc[j] = 0.f;
    const float4* wp = g_w4 + o;
    #pragma unroll 2
    for (int i = 0; i < NN; i++) {
        float4 w = wp[i*NN];
        const float* r = src + i*W;
        float prev = (x0 > 0) ? r[x0-1] : 0.f;
        float cur  = r[x0];
        #pragma unroll
        for (int j = 0; j < LEN; j++) {
            float nxt = (x0 + j + 1 < W) ? r[x0 + j + 1] : 0.f;
            acc[j] += w.x*prev + w.y*cur + w.z*nxt;
            prev = cur; cur = nxt;
        }
    }
}

// one block per batch element; fs aliased with A1 -> smem 72080 B -> 3 CTAs/SM.
__global__ __launch_bounds__(256, 3) void k_st(int t,
        const float* __restrict__ gc1, const float* __restrict__ gc2,
        const float* __restrict__ cb,  const float* __restrict__ lw,
        const float* __restrict__ lbv) {
    extern __shared__ float sm[];
    float* fsA1  = sm;            // union: fs (2484) then A1 (2700)
    float* adj   = fsA1 + 2760;   // 8100
    float* L     = adj + 8100;    // 2430
    float* A2    = L + 2430;      // 2700
    float* gc1s  = A2 + 2700;     // 810
    float* gc2s  = gc1s + 810;    // 900
    float* biasS = gc2s + 900;    // 96
    float* gls   = biasS + 96;    // 32
    float* meanS = gls + 32;      // 96
    float* dinvS = meanS + 96;    // 96  -> total 18020 floats

    int b = blockIdx.x, tid = threadIdx.x;
    const float* seq = g_seq + (size_t)t*BB*NFD + (size_t)b*NFD;
    const float* gsp = g_gsum + t*HH;
    float* fs = fsA1;
    float* A1 = fsA1;

    for (int i = tid; i < NFD/2; i += 256)
        ((float2*)fs)[i] = ((const float2*)seq)[i];
    for (int i = tid; i < FF*HH; i += 256) gc1s[i] = gc1[i];
    for (int i = tid; i < HH*HH; i += 256) gc2s[i] = gc2[i];
    if (tid < NN) biasS[tid] = cb[tid];
    if (tid < FF) {
        const float inv = 1.f/((float)BB*(float)NN);
        float s = lbv[tid];
        #pragma unroll
        for (int h = 0; h < HH; h++) s += lw[tid*HH + h]*gsp[h]*inv;
        gls[tid] = s;
    }
    __syncthreads();

    if (tid < NN) {
        float s = 0.f;
        #pragma unroll
        for (int f = 0; f < FF; f++) s += fs[tid*FF + f];
        meanS[tid] = s*(1.f/27.f);
    }
    if (tid < 225) {                 // gram 6x6 tiles, single pass
        int n0 = (tid/15)*6, m0 = (tid%15)*6;
        float acc[6][6];
        #pragma unroll
        for (int i = 0; i < 6; i++)
            #pragma unroll
            for (int j = 0; j < 6; j++) acc[i][j] = 0.f;
        for (int k = 0; k < FF; k++) {
            float av[6], bv[6];
            #pragma unroll
            for (int j = 0; j < 6; j++) av[j] = fs[(n0+j)*FF + k];
            #pragma unroll
            for (int j = 0; j < 6; j++) bv[j] = fs[(m0+j)*FF + k];
            #pragma unroll
            for (int i = 0; i < 6; i++)
                #pragma unroll
                for (int j = 0; j < 6; j++) acc[i][j] += av[i]*bv[j];
        }
        #pragma unroll
        for (int i = 0; i < 6; i++)
            #pragma unroll
            for (int j = 0; j < 6; j++) adj[(n0+i)*NN + m0+j] = acc[i][j];
    }
    __syncthreads();
    if (tid < NN) {
        float mn = meanS[tid];
        dinvS[tid] = rsqrtf(adj[tid*NN + tid] - 27.f*mn*mn);
    }
    __syncthreads();
    for (int i = tid; i < NN*NN; i += 256) {
        int n = i/NN, m = i%NN;
        adj[i] = (adj[i] - 27.f*meanS[n]*meanS[m])*dinvS[n]*dinvS[m];
    }
    if (tid < 180) {                 // conv1 -> L (last use of fs)
        int o = tid >> 1, half = tid & 1;
        int x0 = half ? 13 : 0, len = half ? 14 : 13;
        float a[14];
        convAccR<14,FF>(fs, a, o, x0);
        float bo = biasS[o];
        #pragma unroll
        for (int j = 0; j < 14; j++)
            if (j < len) L[o*FF + x0 + j] = a[j] + bo + gls[x0 + j];
    }
    __syncthreads();
    if (tid < 180) {                 // X1 = L @ gc1 -> A1 (fs dead)
        int n0 = (tid/6)*3, h0 = (tid%6)*5;
        float acc0[5] = {0,0,0,0,0}, acc1[5] = {0,0,0,0,0}, acc2[5] = {0,0,0,0,0};
        for (int k = 0; k < FF; k++) {
            float a0 = L[n0*FF + k], a1 = L[(n0+1)*FF + k], a2 = L[(n0+2)*FF + k];
            #pragma unroll
            for (int c = 0; c < 5; c++) {
                float bc = gc1s[k*HH + h0 + c];
                acc0[c] += a0*bc; acc1[c] += a1*bc; acc2[c] += a2*bc;
            }
        }
        #pragma unroll
        for (int c = 0; c < 5; c++) {
            A1[n0*HH + h0 + c] = acc0[c];
            A1[(n0+1)*HH + h0 + c] = acc1[c];
            A1[(n0+2)*HH + h0 + c] = acc2[c];
        }
    }
    __syncthreads();
    if (tid < 180) {                 // S1 = adj @ X1 -> A2
        int n0 = (tid/6)*3, h0 = (tid%6)*5;
        float acc0[5] = {0,0,0,0,0}, acc1[5] = {0,0,0,0,0}, acc2[5] = {0,0,0,0,0};
        for (int m = 0; m < NN; m++) {
            float a0 = adj[n0*NN + m], a1 = adj[(n0+1)*NN + m], a2 = adj[(n0+2)*NN + m];
            #pragma unroll
            for (int c = 0; c < 5; c++) {
                float bc = A1[m*HH + h0 + c];
                acc0[c] += a0*bc; acc1[c] += a1*bc; acc2[c] += a2*bc;
            }
        }
        #pragma unroll
        for (int c = 0; c < 5; c++) {
            A2[n0*HH + h0 + c] = acc0[c];
            A2[(n0+1)*HH + h0 + c] = acc1[c];
            A2[(n0+2)*HH + h0 + c] = acc2[c];
        }
    }
    __syncthreads();
    if (tid < 180) {                 // X2 = S1 @ gc2 -> A1
        int n0 = (tid/6)*3, h0 = (tid%6)*5;
        float acc0[5] = {0,0,0,0,0}, acc1[5] = {0,0,0,0,0}, acc2[5] = {0,0,0,0,0};
        for (int k = 0; k < HH; k++) {
            float a0 = A2[n0*HH + k], a1 = A2[(n0+1)*HH + k], a2 = A2[(n0+2)*HH + k];
            #pragma unroll
            for (int c = 0; c < 5; c++) {
                float bc = gc2s[k*HH + h0 + c];
                acc0[c] += a0*bc; acc1[c] += a1*bc; acc2[c] += a2*bc;
            }
        }
        #pragma unroll
        for (int c = 0; c < 5; c++) {
            A1[n0*HH + h0 + c] = acc0[c];
            A1[(n0+1)*HH + h0 + c] = acc1[c];
            A1[(n0+2)*HH + h0 + c] = acc2[c];
        }
    }
    __syncthreads();
    if (tid < 180) {                 // G = adj @ X2 -> A2
        int n0 = (tid/6)*3, h0 = (tid%6)*5;
        float acc0[5] = {0,0,0,0,0}, acc1[5] = {0,0,0,0,0}, acc2[5] = {0,0,0,0,0};
        for (int m = 0; m < NN; m++) {
            float a0 = adj[n0*NN + m], a1 = adj[(n0+1)*NN + m], a2 = adj[(n0+2)*NN + m];
            #pragma unroll
            for (int c = 0; c < 5; c++) {
                float bc = A1[m*HH + h0 + c];
                acc0[c] += a0*bc; acc1[c] += a1*bc; acc2[c] += a2*bc;
            }
        }
        #pragma unroll
        for (int c = 0; c < 5; c++) {
            A2[n0*HH + h0 + c] = acc0[c];
            A2[(n0+1)*HH + h0 + c] = acc1[c];
            A2[(n0+2)*HH + h0 + c] = acc2[c];
        }
    }
    __syncthreads();
    if (tid < HH) {
        float s = 0.f;
        for (int n = 0; n < NN; n++) s += A2[n*HH + tid];
        atomicAdd(&g_gsum[(t+1)*HH + tid], s);
    }
    if (tid < 180) {                 // conv2 + conf-weighted accumulate
        int o = tid >> 1, half = tid & 1;
        int x0 = half*15;
        float a[15];
        convAccR<15,HH>(A2, a, o, x0);
        float bo = biasS[o];
        float cf = g_conf[b*TT + t];
        float* fo = g_final + (size_t)b*NHD + o*HH + x0;
        if (t == 0) {
            #pragma unroll
            for (int j = 0; j < 15; j++) fo[j] = cf*(a[j] + bo);
        } else {
            #pragma unroll
            for (int j = 0; j < 15; j++) fo[j] += cf*(a[j] + bo);
        }
    }
}

// C[M,N] = A(BN-opt)[M,K] @ W[N,K]^T + bias. 128x64 tile, 8x4 micro-tile.
__global__ __launch_bounds__(256) void k_gemm(const float* __restrict__ A,
        const float* __restrict__ W, const float* __restrict__ bias,
        float* __restrict__ C, int M, int N, int K,
        const float* __restrict__ bnp, const float* __restrict__ bg,
        const float* __restrict__ bb) {
    __shared__ float As[16][128];
    __shared__ float Bs[16][64];
    int tid = threadIdx.x;
    int tx = tid & 15, ty = tid >> 4;
    int n0 = blockIdx.x*64, m0 = blockIdx.y*128;
    int lrA = tid >> 1, lkA = (tid & 1)*8;
    int lrB = tid >> 2, lkB = (tid & 3)*4;

    float acc[8][4];
    #pragma unroll
    for (int i = 0; i < 8; i++)
        #pragma unroll
        for (int j = 0; j < 4; j++) acc[i][j] = 0.f;

    for (int k0 = 0; k0 < K; k0 += 16) {
        #pragma unroll
        for (int i = 0; i < 8; i++) {
            int kk = k0 + lkA + i;
            float a = 0.f;
            if (kk < K) {
                a = A[(size_t)(m0 + lrA)*K + kk];
                if (bnp) a = (a - bnp[kk])*bnp[K + kk]*bg[kk] + bb[kk];
            }
            As[lkA + i][lrA] = a;
        }
        #pragma unroll
        for (int i = 0; i < 4; i++) {
            int kk = k0 + lkB + i;
            Bs[lkB + i][lrB] = (kk < K) ? W[(size_t)(n0 + lrB)*K + kk] : 0.f;
        }
        __syncthreads();
        #pragma unroll
        for (int kk = 0; kk < 16; kk++) {
            float4 a0 = *(const float4*)&As[kk][ty*8];
            float4 a1 = *(const float4*)&As[kk][ty*8 + 4];
            float4 bv = *(const float4*)&Bs[kk][tx*4];
            float av[8] = {a0.x, a0.y, a0.z, a0.w, a1.x, a1.y, a1.z, a1.w};
            float bw[4] = {bv.x, bv.y, bv.z, bv.w};
            #pragma unroll
            for (int i = 0; i < 8; i++)
                #pragma unroll
                for (int j = 0; j < 4; j++) acc[i][j] += av[i]*bw[j];
        }
        __syncthreads();
    }
    float4 bia = *(const float4*)&bias[n0 + tx*4];
    #pragma unroll
    for (int i = 0; i < 8; i++) {
        float4 v = make_float4(acc[i][0] + bia.x, acc[i][1] + bia.y,
                               acc[i][2] + bia.z, acc[i][3] + bia.w);
        *(float4*)&C[(size_t)(m0 + ty*8 + i)*N + n0 + tx*4] = v;
    }
}

__global__ void k_bnstat(const float* __restrict__ Y, int N, float* __restrict__ outp) {
    __shared__ float ss[8][32], qq[8][32];
    int c = threadIdx.x & 31, r0 = threadIdx.x >> 5;
    int col = blockIdx.x*32 + c;
    float s = 0.f, q = 0.f;
    for (int r = r0; r < BB; r += 8) {
        float v = Y[(size_t)r*N + col];
        s += v; q += v*v;
    }
    ss[r0][c] = s; qq[r0][c] = q;
    __syncthreads();
    if (r0 == 0) {
        #pragma unroll
        for (int r = 1; r < 8; r++) { s += ss[r][c]; q += qq[r][c]; }
        float mean = s*(1.f/BB);
        float var = q*(1.f/BB) - mean*mean;
        outp[col] = mean;
        outp[N + col] = rsqrtf(var + 1e-5f);
    }
}

__global__ void k_head(const float* __restrict__ l3w, const float* __restrict__ l3b,
                       const float* __restrict__ bg, const float* __restrict__ bb,
                       float* __restrict__ out) {
    int b = blockIdx.x*8 + (threadIdx.x >> 5);
    int lane = threadIdx.x & 31;
    float a0 = 0.f, a1 = 0.f;
    for (int c = lane; c < 256; c += 32) {
        float v = (g_y2[(size_t)b*256 + c] - g_bn2[c])*g_bn2[256 + c]*bg[c] + bb[c];
        a0 += v*l3w[c];
        a1 += v*l3w[256 + c];
    }
    #pragma unroll
    for (int o = 16; o; o >>= 1) {
        a0 += __shfl_down_sync(0xffffffffu, a0, o);
        a1 += __shfl_down_sync(0xffffffffu, a1, o);
    }
    if (!lane) {
        float z0 = a0 + l3b[0], z1 = a1 + l3b[1];
        float mx = fmaxf(z0, z1);
        float e0 = expf(z0 - mx), e1 = expf(z1 - mx);
        float inv = 1.f/(e0 + e1);
        out[b*2 + 0] = e0*inv;
        out[b*2 + 1] = e1*inv;
    }
}

extern "C" void kernel_launch(void* const* d_in, const int* in_sizes, int n_in,
                              void* d_out, int out_size) {
    const float* fdata = (const float*)d_in[0];
    const float* un_w  = (const float*)d_in[1];
    const float* un_b  = (const float*)d_in[2];
    const float* U1    = (const float*)d_in[3];
    const float* U2    = (const float*)d_in[4];
    const float* U3    = (const float*)d_in[5];
    const float* b_e   = (const float*)d_in[6];
    const float* v_e   = (const float*)d_in[7];
    const float* gc1   = (const float*)d_in[8];
    const float* gc2   = (const float*)d_in[9];
    const float* cnn1w = (const float*)d_in[10];
    const float* cnn1b = (const float*)d_in[11];
    const float* lin_w = (const float*)d_in[12];
    const float* lin_b = (const float*)d_in[13];
    const float* l1_w  = (const float*)d_in[14];
    const float* l1_b  = (const float*)d_in[15];
    const float* bn1g  = (const float*)d_in[16];
    const float* bn1b  = (const float*)d_in[17];
    const float* l2_w  = (const float*)d_in[18];
    const float* l2_b  = (const float*)d_in[19];
    const float* bn2g  = (const float*)d_in[20];
    const float* bn2b  = (const float*)d_in[21];
    const float* l3_w  = (const float*)d_in[22];
    const float* l3_b  = (const float*)d_in[23];
    float* out = (float*)d_out;

    static float* d_bn1p = nullptr;
    static float* d_bn2p = nullptr;
    static float* d_y1p = nullptr;
    static float* d_y2p = nullptr;
    if (!d_bn1p) {
        cudaGetSymbolAddress((void**)&d_bn1p, g_bn1);
        cudaGetSymbolAddress((void**)&d_bn2p, g_bn2);
        cudaGetSymbolAddress((void**)&d_y1p, g_y1);
        cudaGetSymbolAddress((void**)&d_y2p, g_y2);
        cudaFuncSetAttribute(k_att, cudaFuncAttributeMaxDynamicSharedMemorySize, 85000);
        cudaFuncSetAttribute(k_st,  cudaFuncAttributeMaxDynamicSharedMemorySize, 74000);
    }
    float* d_finalp; cudaGetSymbolAddress((void**)&d_finalp, g_final);

    k_init<<<(NN*NN + 255)/256, 256>>>(cnn1w);
    k_att<<<BB, 256, 21188*4>>>(fdata, U1, U2, U3, b_e, v_e, un_w, un_b);
    for (int t = 0; t < TT; t++)
        k_st<<<BB, 256, 18020*4>>>(t, gc1, gc2, cnn1b, lin_w, lin_b);
    dim3 g1(1024/64, BB/128);
    k_gemm<<<g1, 256>>>(d_finalp, l1_w, l1_b, d_y1p, BB, 1024, NHD,
                        nullptr, nullptr, nullptr);
    k_bnstat<<<1024/32, 256>>>(d_y1p, 1024, d_bn1p);
    dim3 g2(256/64, BB/128);
    k_gemm<<<g2, 256>>>(d_y1p, l2_w, l2_b, d_y2p, BB, 256, 1024,
                        d_bn1p, bn1g, bn1b);
    k_bnstat<<<256/32, 256>>>(d_y2p, 256, d_bn2p);
    k_head<<<BB/8, 256>>>(l3_w, l3_b, bn2g, bn2b, out);
}